// round 12
// baseline (speedup 1.0000x reference)
#include <cuda_runtime.h>
#include <cuda_fp16.h>
#include <stdint.h>

#define N_NODES 100000
#define N_EDGES 1600000
#define D_FEAT  64

// Scratch (device globals — no allocs allowed):
__device__ int    g_row_ptr[N_NODES + 1];
__device__ __half g_emb_h[N_NODES * D_FEAT];   // 12.8 MB fp16 shadow (128B per row)

// Merged prep: fp32->fp16 convert (8 floats/thread) AND CSR boundary fill.
__global__ void prep_kernel(const float* __restrict__ embeds,
                            const int*   __restrict__ rows,
                            int n_edges) {
    int i = blockIdx.x * blockDim.x + threadIdx.x;

    if (i < N_NODES * D_FEAT / 8) {
        const float4* src = reinterpret_cast<const float4*>(embeds) + (size_t)i * 2;
        float4 f0 = src[0];
        float4 f1 = src[1];
        union { __half2 h[4]; uint4 u; } p;
        p.h[0] = __floats2half2_rn(f0.x, f0.y);
        p.h[1] = __floats2half2_rn(f0.z, f0.w);
        p.h[2] = __floats2half2_rn(f1.x, f1.y);
        p.h[3] = __floats2half2_rn(f1.z, f1.w);
        reinterpret_cast<uint4*>(g_emb_h)[i] = p.u;
    }

    if (i < n_edges) {
        int r = rows[i];
        int prev = (i == 0) ? -1 : rows[i - 1];
        for (int rr = prev + 1; rr <= r; ++rr) {
            g_row_ptr[rr] = i;
        }
        if (i == n_edges - 1) {
            for (int rr = r + 1; rr <= N_NODES; ++rr) {
                g_row_ptr[rr] = n_edges;
            }
        }
    }
}

// drain 4 half2 partials into fp32 accumulators
__device__ __forceinline__ void drain(__half2 P0, __half2 P1,
                                      __half2 P2, __half2 P3,
                                      float4& aA, float4& aB) {
    float2 f;
    f = __half22float2(P0);  aA.x += f.x;  aA.y += f.y;
    f = __half22float2(P1);  aA.z += f.x;  aA.w += f.y;
    f = __half22float2(P2);  aB.x += f.x;  aB.y += f.y;
    f = __half22float2(P3);  aB.z += f.x;  aB.w += f.y;
}

// SpMM: one WARP per output row — uniform control flow, no quarter divergence.
// Lane layout: q = lane>>3 (edge group), s = lane&7 (uint4 feature slice).
// Main block = 16 edges: each lane handles edges {e+2q, e+2q+1, e+8+2q,
// e+8+2q+1} with depth-4 half2 accumulation, drained to fp32 per block.
// All cols/vals loads are SCALAR (no alignment requirement). Remainder:
// one predicated 8-edge block + one clamped 2-edge block. Epilogue folds
// the 4 groups with shfl_down(16, 8).
__global__ void __launch_bounds__(256) spmm_warp_per_row(
    const int*   __restrict__ cols,
    const float* __restrict__ vals,
    float*       __restrict__ out)
{
    int row  = (blockIdx.x * blockDim.x + threadIdx.x) >> 5;
    int lane = threadIdx.x & 31;
    if (row >= N_NODES) return;

    const int q = lane >> 3;
    const int s = lane & 7;

    int e  = g_row_ptr[row];
    int hi = g_row_ptr[row + 1];

    const uint4* __restrict__ emb = reinterpret_cast<const uint4*>(g_emb_h);

    float4 aA = make_float4(0.f, 0.f, 0.f, 0.f);
    float4 aB = make_float4(0.f, 0.f, 0.f, 0.f);

    // main: 16 edges per iteration (4 edges per lane, depth-4 half2)
    for (; e + 15 < hi; e += 16) {
        int   i0 = e + 2 * q;
        int   i2 = e + 8 + 2 * q;
        int   c0 = cols[i0];
        int   c1 = cols[i0 + 1];
        int   c2 = cols[i2];
        int   c3 = cols[i2 + 1];
        float v0 = vals[i0];
        float v1 = vals[i0 + 1];
        float v2 = vals[i2];
        float v3 = vals[i2 + 1];

        uint4 r0 = emb[(size_t)c0 * 8 + s];
        uint4 r1 = emb[(size_t)c1 * 8 + s];
        uint4 r2 = emb[(size_t)c2 * 8 + s];
        uint4 r3 = emb[(size_t)c3 * 8 + s];

        __half2 h0 = __float2half2_rn(v0);
        __half2 h1 = __float2half2_rn(v1);
        __half2 h2 = __float2half2_rn(v2);
        __half2 h3 = __float2half2_rn(v3);

        __half2 P0 = __hmul2(h0, *reinterpret_cast<__half2*>(&r0.x));
        __half2 P1 = __hmul2(h0, *reinterpret_cast<__half2*>(&r0.y));
        __half2 P2 = __hmul2(h0, *reinterpret_cast<__half2*>(&r0.z));
        __half2 P3 = __hmul2(h0, *reinterpret_cast<__half2*>(&r0.w));
        P0 = __hfma2(h1, *reinterpret_cast<__half2*>(&r1.x), P0);
        P1 = __hfma2(h1, *reinterpret_cast<__half2*>(&r1.y), P1);
        P2 = __hfma2(h1, *reinterpret_cast<__half2*>(&r1.z), P2);
        P3 = __hfma2(h1, *reinterpret_cast<__half2*>(&r1.w), P3);
        P0 = __hfma2(h2, *reinterpret_cast<__half2*>(&r2.x), P0);
        P1 = __hfma2(h2, *reinterpret_cast<__half2*>(&r2.y), P1);
        P2 = __hfma2(h2, *reinterpret_cast<__half2*>(&r2.z), P2);
        P3 = __hfma2(h2, *reinterpret_cast<__half2*>(&r2.w), P3);
        P0 = __hfma2(h3, *reinterpret_cast<__half2*>(&r3.x), P0);
        P1 = __hfma2(h3, *reinterpret_cast<__half2*>(&r3.y), P1);
        P2 = __hfma2(h3, *reinterpret_cast<__half2*>(&r3.z), P2);
        P3 = __hfma2(h3, *reinterpret_cast<__half2*>(&r3.w), P3);

        drain(P0, P1, P2, P3, aA, aB);
    }

    // one 8-edge block (2 edges per lane, depth 2)
    if (e + 7 < hi) {
        int   i0 = e + 2 * q;
        int   c0 = cols[i0];
        int   c1 = cols[i0 + 1];
        float v0 = vals[i0];
        float v1 = vals[i0 + 1];
        uint4 r0 = emb[(size_t)c0 * 8 + s];
        uint4 r1 = emb[(size_t)c1 * 8 + s];
        __half2 h0 = __float2half2_rn(v0);
        __half2 h1 = __float2half2_rn(v1);
        __half2 P0 = __hmul2(h0, *reinterpret_cast<__half2*>(&r0.x));
        __half2 P1 = __hmul2(h0, *reinterpret_cast<__half2*>(&r0.y));
        __half2 P2 = __hmul2(h0, *reinterpret_cast<__half2*>(&r0.z));
        __half2 P3 = __hmul2(h0, *reinterpret_cast<__half2*>(&r0.w));
        P0 = __hfma2(h1, *reinterpret_cast<__half2*>(&r1.x), P0);
        P1 = __hfma2(h1, *reinterpret_cast<__half2*>(&r1.y), P1);
        P2 = __hfma2(h1, *reinterpret_cast<__half2*>(&r1.z), P2);
        P3 = __hfma2(h1, *reinterpret_cast<__half2*>(&r1.w), P3);
        drain(P0, P1, P2, P3, aA, aB);
        e += 8;
    }

    // remainder 1..7 edges: clamped predicated 2-edge block per lane
    int rem = hi - e;
    if (rem > 0) {
        int  i0 = e + 2 * q;
        int  i1 = i0 + 1;
        bool ok0 = (2 * q)     < rem;
        bool ok1 = (2 * q + 1) < rem;
        int   c0 = cols[ok0 ? i0 : e];      // e always valid (rem>0)
        int   c1 = cols[ok1 ? i1 : e];
        float v0 = ok0 ? vals[i0] : 0.f;
        float v1 = ok1 ? vals[i1] : 0.f;
        uint4 r0 = emb[(size_t)c0 * 8 + s];
        uint4 r1 = emb[(size_t)c1 * 8 + s];
        __half2 h0 = __float2half2_rn(v0);
        __half2 h1 = __float2half2_rn(v1);
        __half2 P0 = __hmul2(h0, *reinterpret_cast<__half2*>(&r0.x));
        __half2 P1 = __hmul2(h0, *reinterpret_cast<__half2*>(&r0.y));
        __half2 P2 = __hmul2(h0, *reinterpret_cast<__half2*>(&r0.z));
        __half2 P3 = __hmul2(h0, *reinterpret_cast<__half2*>(&r0.w));
        P0 = __hfma2(h1, *reinterpret_cast<__half2*>(&r1.x), P0);
        P1 = __hfma2(h1, *reinterpret_cast<__half2*>(&r1.y), P1);
        P2 = __hfma2(h1, *reinterpret_cast<__half2*>(&r1.z), P2);
        P3 = __hfma2(h1, *reinterpret_cast<__half2*>(&r1.w), P3);
        drain(P0, P1, P2, P3, aA, aB);
    }

    // fold groups q3->q1, q2->q0 (shfl 16), then q1->q0 (shfl 8)
    #pragma unroll
    for (int off = 16; off >= 8; off >>= 1) {
        aA.x += __shfl_down_sync(0xffffffffu, aA.x, off);
        aA.y += __shfl_down_sync(0xffffffffu, aA.y, off);
        aA.z += __shfl_down_sync(0xffffffffu, aA.z, off);
        aA.w += __shfl_down_sync(0xffffffffu, aA.w, off);
        aB.x += __shfl_down_sync(0xffffffffu, aB.x, off);
        aB.y += __shfl_down_sync(0xffffffffu, aB.y, off);
        aB.z += __shfl_down_sync(0xffffffffu, aB.z, off);
        aB.w += __shfl_down_sync(0xffffffffu, aB.w, off);
    }

    if (q == 0) {
        float4* o = reinterpret_cast<float4*>(out) + (size_t)row * 16 + s * 2;
        o[0] = aA;
        o[1] = aB;
    }
}

extern "C" void kernel_launch(void* const* d_in, const int* in_sizes, int n_in,
                              void* d_out, int out_size) {
    const int*   rows   = (const int*)d_in[0];
    const int*   cols   = (const int*)d_in[1];
    const float* vals   = (const float*)d_in[2];
    const float* embeds = (const float*)d_in[3];
    float*       out    = (float*)d_out;

    int n_edges = in_sizes[0];

    {
        int total = n_edges;
        int threads = 256;
        prep_kernel<<<(total + threads - 1) / threads, threads>>>(embeds, rows, n_edges);
    }
    {
        int threads = 256;
        int blocks = (N_NODES * 32 + threads - 1) / threads;  // 12500
        spmm_warp_per_row<<<blocks, threads>>>(cols, vals, out);
    }
}

// round 13
// speedup vs baseline: 1.2358x; 1.2358x over previous
#include <cuda_runtime.h>
#include <cuda_fp16.h>
#include <stdint.h>

#define N_NODES 100000
#define N_EDGES 1600000
#define D_FEAT  64

// Scratch (device globals — no allocs allowed):
__device__ int    g_row_ptr[N_NODES + 1];
__device__ __half g_emb_h[N_NODES * D_FEAT];   // 12.8 MB fp16 shadow (128B per row)

// Merged prep: fp32->fp16 convert (8 floats/thread) AND CSR boundary fill.
__global__ void prep_kernel(const float* __restrict__ embeds,
                            const int*   __restrict__ rows,
                            int n_edges) {
    int i = blockIdx.x * blockDim.x + threadIdx.x;

    if (i < N_NODES * D_FEAT / 8) {
        const float4* src = reinterpret_cast<const float4*>(embeds) + (size_t)i * 2;
        float4 f0 = src[0];
        float4 f1 = src[1];
        union { __half2 h[4]; uint4 u; } p;
        p.h[0] = __floats2half2_rn(f0.x, f0.y);
        p.h[1] = __floats2half2_rn(f0.z, f0.w);
        p.h[2] = __floats2half2_rn(f1.x, f1.y);
        p.h[3] = __floats2half2_rn(f1.z, f1.w);
        reinterpret_cast<uint4*>(g_emb_h)[i] = p.u;
    }

    if (i < n_edges) {
        int r = rows[i];
        int prev = (i == 0) ? -1 : rows[i - 1];
        for (int rr = prev + 1; rr <= r; ++rr) {
            g_row_ptr[rr] = i;
        }
        if (i == n_edges - 1) {
            for (int rr = r + 1; rr <= N_NODES; ++rr) {
                g_row_ptr[rr] = n_edges;
            }
        }
    }
}

// fp32-exact single-edge accumulate (peel/tail path).
__device__ __forceinline__ void edge_f32(const uint4* __restrict__ emb,
                                         const int* __restrict__ cols,
                                         const float* __restrict__ vals,
                                         int e, int lane8,
                                         float4& aA, float4& aB) {
    int   c = cols[e];
    float v = vals[e];
    uint4 r = emb[(size_t)c * 8 + lane8];
    float2 f0 = __half22float2(*reinterpret_cast<__half2*>(&r.x));
    float2 f1 = __half22float2(*reinterpret_cast<__half2*>(&r.y));
    float2 f2 = __half22float2(*reinterpret_cast<__half2*>(&r.z));
    float2 f3 = __half22float2(*reinterpret_cast<__half2*>(&r.w));
    aA.x += v * f0.x;  aA.y += v * f0.y;
    aA.z += v * f1.x;  aA.w += v * f1.y;
    aB.x += v * f2.x;  aB.y += v * f2.y;
    aB.z += v * f3.x;  aB.w += v * f3.y;
}

// SpMM: one quarter-warp (8 lanes) per output row, fp16 table.
// Exact R7 structure (best so far), with forced 8 blocks/SM (<=32 regs) to
// raise occupancy 60% -> ~90% and push LTS utilization toward the cap.
__global__ void __launch_bounds__(256, 8) spmm_qwarp_per_row(
    const int*   __restrict__ cols,
    const float* __restrict__ vals,
    float*       __restrict__ out)
{
    int row   = (blockIdx.x * blockDim.x + threadIdx.x) >> 3;
    int lane8 = threadIdx.x & 7;
    if (row >= N_NODES) return;

    int e  = g_row_ptr[row];
    int hi = g_row_ptr[row + 1];

    const uint4* __restrict__ emb = reinterpret_cast<const uint4*>(g_emb_h);

    float4 aA = make_float4(0.f, 0.f, 0.f, 0.f);
    float4 aB = make_float4(0.f, 0.f, 0.f, 0.f);

    // peel one edge if start is odd (enables int2/float2 packed loads)
    if ((e & 1) && e < hi) {
        edge_f32(emb, cols, vals, e, lane8, aA, aB);
        ++e;
    }

    // main loop: 4 edges per group, half2 accumulation, drain each group
    for (; e + 3 < hi; e += 4) {
        int2   c01 = *reinterpret_cast<const int2*>(cols + e);
        int2   c23 = *reinterpret_cast<const int2*>(cols + e + 2);
        float2 v01 = *reinterpret_cast<const float2*>(vals + e);
        float2 v23 = *reinterpret_cast<const float2*>(vals + e + 2);

        uint4 r0 = emb[(size_t)c01.x * 8 + lane8];
        uint4 r1 = emb[(size_t)c01.y * 8 + lane8];
        uint4 r2 = emb[(size_t)c23.x * 8 + lane8];
        uint4 r3 = emb[(size_t)c23.y * 8 + lane8];

        __half2 h0 = __float2half2_rn(v01.x);
        __half2 h1 = __float2half2_rn(v01.y);
        __half2 h2 = __float2half2_rn(v23.x);
        __half2 h3 = __float2half2_rn(v23.y);

        __half2 p0 = __hmul2(h0, *reinterpret_cast<__half2*>(&r0.x));
        __half2 p1 = __hmul2(h0, *reinterpret_cast<__half2*>(&r0.y));
        __half2 p2 = __hmul2(h0, *reinterpret_cast<__half2*>(&r0.z));
        __half2 p3 = __hmul2(h0, *reinterpret_cast<__half2*>(&r0.w));

        p0 = __hfma2(h1, *reinterpret_cast<__half2*>(&r1.x), p0);
        p1 = __hfma2(h1, *reinterpret_cast<__half2*>(&r1.y), p1);
        p2 = __hfma2(h1, *reinterpret_cast<__half2*>(&r1.z), p2);
        p3 = __hfma2(h1, *reinterpret_cast<__half2*>(&r1.w), p3);

        p0 = __hfma2(h2, *reinterpret_cast<__half2*>(&r2.x), p0);
        p1 = __hfma2(h2, *reinterpret_cast<__half2*>(&r2.y), p1);
        p2 = __hfma2(h2, *reinterpret_cast<__half2*>(&r2.z), p2);
        p3 = __hfma2(h2, *reinterpret_cast<__half2*>(&r2.w), p3);

        p0 = __hfma2(h3, *reinterpret_cast<__half2*>(&r3.x), p0);
        p1 = __hfma2(h3, *reinterpret_cast<__half2*>(&r3.y), p1);
        p2 = __hfma2(h3, *reinterpret_cast<__half2*>(&r3.z), p2);
        p3 = __hfma2(h3, *reinterpret_cast<__half2*>(&r3.w), p3);

        // drain group to fp32
        float2 f;
        f = __half22float2(p0);  aA.x += f.x;  aA.y += f.y;
        f = __half22float2(p1);  aA.z += f.x;  aA.w += f.y;
        f = __half22float2(p2);  aB.x += f.x;  aB.y += f.y;
        f = __half22float2(p3);  aB.z += f.x;  aB.w += f.y;
    }

    // tail (<=3 edges): exact fp32 path
    for (; e < hi; ++e) {
        edge_f32(emb, cols, vals, e, lane8, aA, aB);
    }

    // 8 lanes x 32B = 256B coalesced output row
    float4* o = reinterpret_cast<float4*>(out) + (size_t)row * 16 + lane8 * 2;
    o[0] = aA;
    o[1] = aB;
}

extern "C" void kernel_launch(void* const* d_in, const int* in_sizes, int n_in,
                              void* d_out, int out_size) {
    const int*   rows   = (const int*)d_in[0];
    const int*   cols   = (const int*)d_in[1];
    const float* vals   = (const float*)d_in[2];
    const float* embeds = (const float*)d_in[3];
    float*       out    = (float*)d_out;

    int n_edges = in_sizes[0];

    {
        int total = n_edges;
        int threads = 256;
        prep_kernel<<<(total + threads - 1) / threads, threads>>>(embeds, rows, n_edges);
    }
    {
        int threads = 256;
        int blocks = (N_NODES * 8 + threads - 1) / threads;
        spmm_qwarp_per_row<<<blocks, threads>>>(cols, vals, out);
    }
}